// round 1
// baseline (speedup 1.0000x reference)
#include <cuda_runtime.h>

// Problem constants (fixed by the reference)
#define K_VOL    27
#define M_PAIRS  100000
#define C_IN     64
#define C_OUT    64
#define N_OUT    200000

#define TILE_M   128
#define TILES_PER_K ((M_PAIRS + TILE_M - 1) / TILE_M)   // 782

// ---------------------------------------------------------------------------
// Kernel 1: out[row][c] = bias[c]   (out_size = N_OUT * C_OUT floats)
// ---------------------------------------------------------------------------
__global__ void init_bias_kernel(float* __restrict__ out,
                                 const float* __restrict__ bias,
                                 int total_f4) {
    const float4* b4 = (const float4*)bias;   // 16 float4 = 64 floats
    int idx = blockIdx.x * blockDim.x + threadIdx.x;
    int stride = gridDim.x * blockDim.x;
    for (int i = idx; i < total_f4; i += stride) {
        // row stride is 16 float4s -> column index is (i & 15)
        ((float4*)out)[i] = b4[i & 15];
    }
}

// ---------------------------------------------------------------------------
// Kernel 2: per (k, m-tile): gather -> 128x64x64 GEMM -> scatter atomicAdd
// blockDim = 256.  Thread tile: 8 rows x 4 cols (16x16 thread grid).
// smem: Bs (kernel slice) 16KB + As (gathered rows) 32KB = 48KB.
// ---------------------------------------------------------------------------
__global__ __launch_bounds__(256, 4)
void conv_gather_gemm_scatter(const float* __restrict__ in_feats,
                              const float* __restrict__ kernel,
                              const int*   __restrict__ imap,
                              const int*   __restrict__ omap,
                              float*       __restrict__ out) {
    __shared__ float Bs[C_IN * C_OUT];    // [ci][co]  16 KB
    __shared__ float As[TILE_M * C_IN];   // [row][ci] 32 KB

    const int b    = blockIdx.x;
    const int k    = b / TILES_PER_K;
    const int tile = b % TILES_PER_K;
    const int m0   = tile * TILE_M;
    const int mrem = min(TILE_M, M_PAIRS - m0);

    const int tid = threadIdx.x;

    // ---- load kernel[k] slice into smem (1024 float4 / 256 threads = 4 each)
    {
        const float4* kb = (const float4*)(kernel + (size_t)k * C_IN * C_OUT);
        float4* bs4 = (float4*)Bs;
        #pragma unroll
        for (int i = 0; i < 4; i++)
            bs4[tid + i * 256] = kb[tid + i * 256];
    }

    // ---- gather: 2 threads per row, 8 float4 each (row = 16 float4 = 256B)
    {
        const int r    = tid >> 1;       // 0..127
        const int half = tid & 1;
        int grow = -1;
        if (r < mrem)
            grow = __ldg(&imap[(size_t)k * M_PAIRS + m0 + r]);
        const float4* in4 = (const float4*)in_feats;
        float4* as4 = (float4*)As;
        #pragma unroll
        for (int p = 0; p < 8; p++) {
            int v = half * 8 + p;
            float4 val = make_float4(0.f, 0.f, 0.f, 0.f);
            if (grow >= 0) val = in4[(size_t)grow * 16 + v];
            as4[r * 16 + v] = val;       // rows beyond mrem zero-filled
        }
    }
    __syncthreads();

    // ---- register-tiled GEMM: C[128][64] , thread = 8 rows x 4 cols
    const int tx = tid & 15;             // col group: cols tx*4 .. tx*4+3
    const int ty = tid >> 4;             // row group: rows ty*8 .. ty*8+7

    float acc[8][4];
    #pragma unroll
    for (int i = 0; i < 8; i++)
        #pragma unroll
        for (int j = 0; j < 4; j++)
            acc[i][j] = 0.f;

    #pragma unroll 8
    for (int kk = 0; kk < C_IN; kk++) {
        float bv[4];
        #pragma unroll
        for (int j = 0; j < 4; j++)
            bv[j] = Bs[kk * C_OUT + tx * 4 + j];
        #pragma unroll
        for (int i = 0; i < 8; i++) {
            float av = As[(ty * 8 + i) * C_IN + kk];
            #pragma unroll
            for (int j = 0; j < 4; j++)
                acc[i][j] = fmaf(av, bv[j], acc[i][j]);
        }
    }

    // ---- scatter-add (REDG; rows >= mrem skipped, their acc is 0 anyway)
    #pragma unroll
    for (int i = 0; i < 8; i++) {
        const int rr = ty * 8 + i;
        if (rr < mrem) {
            const int orow = __ldg(&omap[(size_t)k * M_PAIRS + m0 + rr]);
            float* dst = out + (size_t)orow * C_OUT + tx * 4;
            atomicAdd(dst + 0, acc[i][0]);
            atomicAdd(dst + 1, acc[i][1]);
            atomicAdd(dst + 2, acc[i][2]);
            atomicAdd(dst + 3, acc[i][3]);
        }
    }
}

// ---------------------------------------------------------------------------
// Launch
// ---------------------------------------------------------------------------
extern "C" void kernel_launch(void* const* d_in, const int* in_sizes, int n_in,
                              void* d_out, int out_size) {
    const float* in_feats = (const float*)d_in[0];  // [N_IN, 64]
    const float* kernel   = (const float*)d_in[1];  // [27, 64, 64]
    const float* bias     = (const float*)d_in[2];  // [64]
    const int*   imap     = (const int*)d_in[3];    // [27, 100000]
    const int*   omap     = (const int*)d_in[4];    // [27, 100000]
    float* out = (float*)d_out;                     // [N_OUT, 64]

    (void)in_sizes; (void)n_in; (void)out_size;

    // 1) out = bias (broadcast rows)
    const int total_f4 = N_OUT * (C_OUT / 4);       // 3.2M float4
    init_bias_kernel<<<2048, 256>>>(out, bias, total_f4);

    // 2) gather -> GEMM -> scatter for all 27 offsets
    conv_gather_gemm_scatter<<<K_VOL * TILES_PER_K, 256>>>(
        in_feats, kernel, imap, omap, out);
}

// round 3
// speedup vs baseline: 1.6232x; 1.6232x over previous
#include <cuda_runtime.h>
#include <cuda_bf16.h>
#include <cstdint>

// ---------------------------------------------------------------------------
// Problem constants
// ---------------------------------------------------------------------------
#define K_VOL    27
#define M_PAIRS  100000
#define C_IN     64
#define C_OUT    64
#define N_IN     200000
#define N_OUT    200000

#define TILE_M   128
#define TILES_PER_K ((M_PAIRS + TILE_M - 1) / TILE_M)   // 782

// bf16 hi/lo scratch (device globals: allocation-free scratch)
__device__ __nv_bfloat16 g_A_hi[(size_t)N_IN * C_IN];
__device__ __nv_bfloat16 g_A_lo[(size_t)N_IN * C_IN];
__device__ __nv_bfloat16 g_B_hi[K_VOL * C_IN * C_OUT];  // transposed: [k][co][ci]
__device__ __nv_bfloat16 g_B_lo[K_VOL * C_IN * C_OUT];

// ---------------------------------------------------------------------------
// smem layout (bytes). Row stride padded 128B -> 144B for conflict-free LDSM.
//   A_hi: 128 rows * 144 = 18432      [0      .. 18432)
//   A_lo: 128 rows * 144 = 18432      [18432  .. 36864)
//   B_hi:  64 rows * 144 =  9216      [36864  .. 46080)
//   B_lo:  64 rows * 144 =  9216      [46080  .. 55296)
//   stage (reuses A region): 128 rows * 72 floats * 4 = 36864
// ---------------------------------------------------------------------------
#define ASTRIDE   144
#define OFF_AH    0
#define OFF_AL    18432
#define OFF_BH    36864
#define OFF_BL    46080
#define SMEM_BYTES 55296
#define STAGE_STRIDE 72   // floats

__device__ __forceinline__ uint32_t smem_u32(const void* p) {
    uint32_t a;
    asm("{ .reg .u64 t; cvta.to.shared.u64 t, %1; cvt.u32.u64 %0, t; }" : "=r"(a) : "l"(p));
    return a;
}

__device__ __forceinline__ void ldsm_x4(uint32_t& r0, uint32_t& r1, uint32_t& r2, uint32_t& r3,
                                        uint32_t addr) {
    asm volatile("ldmatrix.sync.aligned.m8n8.x4.shared.b16 {%0,%1,%2,%3}, [%4];"
                 : "=r"(r0), "=r"(r1), "=r"(r2), "=r"(r3) : "r"(addr));
}

__device__ __forceinline__ void mma16816(float& c0, float& c1, float& c2, float& c3,
                                         uint32_t a0, uint32_t a1, uint32_t a2, uint32_t a3,
                                         uint32_t b0, uint32_t b1) {
    asm volatile(
        "mma.sync.aligned.m16n8k16.row.col.f32.bf16.bf16.f32 "
        "{%0,%1,%2,%3}, {%4,%5,%6,%7}, {%8,%9}, {%0,%1,%2,%3};"
        : "+f"(c0), "+f"(c1), "+f"(c2), "+f"(c3)
        : "r"(a0), "r"(a1), "r"(a2), "r"(a3), "r"(b0), "r"(b1));
}

// ---------------------------------------------------------------------------
// Kernel A: split fp32 features into bf16 hi + lo
// ---------------------------------------------------------------------------
__global__ void split_feats_kernel(const float* __restrict__ in, int total4) {
    int idx = blockIdx.x * blockDim.x + threadIdx.x;
    int stride = gridDim.x * blockDim.x;
    const float4* in4 = (const float4*)in;
    __nv_bfloat162* hi2 = (__nv_bfloat162*)g_A_hi;
    __nv_bfloat162* lo2 = (__nv_bfloat162*)g_A_lo;
    for (int i = idx; i < total4; i += stride) {
        float4 v = in4[i];
        __nv_bfloat16 h0 = __float2bfloat16_rn(v.x);
        __nv_bfloat16 h1 = __float2bfloat16_rn(v.y);
        __nv_bfloat16 h2 = __float2bfloat16_rn(v.z);
        __nv_bfloat16 h3 = __float2bfloat16_rn(v.w);
        __nv_bfloat16 l0 = __float2bfloat16_rn(v.x - __bfloat162float(h0));
        __nv_bfloat16 l1 = __float2bfloat16_rn(v.y - __bfloat162float(h1));
        __nv_bfloat16 l2 = __float2bfloat16_rn(v.z - __bfloat162float(h2));
        __nv_bfloat16 l3 = __float2bfloat16_rn(v.w - __bfloat162float(h3));
        hi2[i * 2 + 0] = __halves2bfloat162(h0, h1);
        hi2[i * 2 + 1] = __halves2bfloat162(h2, h3);
        lo2[i * 2 + 0] = __halves2bfloat162(l0, l1);
        lo2[i * 2 + 1] = __halves2bfloat162(l2, l3);
    }
}

// ---------------------------------------------------------------------------
// Kernel B: split + transpose weights: g_B[k][co][ci] = split(W[k][ci][co])
// ---------------------------------------------------------------------------
__global__ void split_weights_kernel(const float* __restrict__ W) {
    int idx = blockIdx.x * blockDim.x + threadIdx.x;
    if (idx >= K_VOL * C_IN * C_OUT) return;
    int k  = idx / (C_IN * C_OUT);
    int r  = idx % (C_IN * C_OUT);
    int ci = r / C_OUT;
    int co = r % C_OUT;
    float x = W[idx];
    __nv_bfloat16 h = __float2bfloat16_rn(x);
    __nv_bfloat16 l = __float2bfloat16_rn(x - __bfloat162float(h));
    int didx = k * (C_IN * C_OUT) + co * C_IN + ci;
    g_B_hi[didx] = h;
    g_B_lo[didx] = l;
}

// ---------------------------------------------------------------------------
// Kernel C: out[row][c] = bias[c]
// ---------------------------------------------------------------------------
__global__ void init_bias_kernel(float* __restrict__ out, const float* __restrict__ bias,
                                 int total4) {
    const float4* b4 = (const float4*)bias;
    int idx = blockIdx.x * blockDim.x + threadIdx.x;
    int stride = gridDim.x * blockDim.x;
    for (int i = idx; i < total4; i += stride)
        ((float4*)out)[i] = b4[i & 15];
}

// ---------------------------------------------------------------------------
// Kernel D: per (k, m-tile): gather -> HMMA bf16-split GEMM -> v4 red scatter
// 256 threads (8 warps). Warp w computes rows 16w..16w+15, all 64 cols.
// ---------------------------------------------------------------------------
__global__ __launch_bounds__(256, 3)
void conv_mma_kernel(const int* __restrict__ imap, const int* __restrict__ omap,
                     float* __restrict__ out) {
    extern __shared__ char smem[];
    const uint32_t sbase = smem_u32(smem);

    const int tid  = threadIdx.x;
    const int wid  = tid >> 5;
    const int lane = tid & 31;

    const int b    = blockIdx.x;
    const int k    = b / TILES_PER_K;
    const int tile = b % TILES_PER_K;
    const int m0   = tile * TILE_M;
    const int mrem = min(TILE_M, M_PAIRS - m0);

    // ---- load B tiles: 128 tasks = 64 rows x {hi,lo}; threads 0..127 ----
    if (tid < 128) {
        const int row = tid & 63;
        const bool lo = tid >= 64;
        const __nv_bfloat16* src = (lo ? g_B_lo : g_B_hi) + (size_t)k * 4096 + row * 64;
        const uint4* s4 = (const uint4*)src;
        char* dst = smem + (lo ? OFF_BL : OFF_BH) + row * ASTRIDE;
        #pragma unroll
        for (int j = 0; j < 8; j++)
            *(uint4*)(dst + j * 16) = s4[j];
    }

    // ---- gather A rows: 256 tasks = 128 rows x {hi,lo} ----
    {
        const int row = tid & 127;
        const bool lo = tid >= 128;
        char* dst = smem + (lo ? OFF_AL : OFF_AH) + row * ASTRIDE;
        if (row < mrem) {
            const int grow = __ldg(&imap[(size_t)k * M_PAIRS + m0 + row]);
            const uint4* s4 = (const uint4*)((lo ? g_A_lo : g_A_hi) + (size_t)grow * C_IN);
            #pragma unroll
            for (int j = 0; j < 8; j++)
                *(uint4*)(dst + j * 16) = s4[j];
        } else {
            const uint4 z = make_uint4(0, 0, 0, 0);
            #pragma unroll
            for (int j = 0; j < 8; j++)
                *(uint4*)(dst + j * 16) = z;
        }
    }
    __syncthreads();

    // ---- per-lane ldmatrix address offsets ----
    // A x4 (m16 x k16): mat = lane>>3
    //   row = (lane&7) + ((lane>>3)&1)*8 ; koff = (lane>>4)*8
    const int a_row  = (lane & 7) + ((lane >> 3) & 1) * 8;
    const int a_koff = (lane >> 4) * 8;
    const uint32_t a_lane_off = (uint32_t)((16 * wid + a_row) * ASTRIDE + a_koff * 2);
    // B x4 (two n8 x k16 tiles): mat = lane>>3
    //   row = (lane&7) + (lane>=16 ? 8 : 0) ; koff = ((lane>>3)&1)*8
    const int b_row  = (lane & 7) + ((lane >> 4) ? 8 : 0);
    const int b_koff = ((lane >> 3) & 1) * 8;
    const uint32_t b_lane_off = (uint32_t)(b_row * ASTRIDE + b_koff * 2);

    // ---- accumulators: 8 n-tiles x 4 regs ----
    float acc[8][4];
    #pragma unroll
    for (int nt = 0; nt < 8; nt++)
        #pragma unroll
        for (int j = 0; j < 4; j++)
            acc[nt][j] = 0.f;

    // ---- 3 products: Ah*Bh, Ah*Bl, Al*Bh ----
    #pragma unroll
    for (int p = 0; p < 3; p++) {
        const uint32_t abase = sbase + (p == 2 ? OFF_AL : OFF_AH) + a_lane_off;
        const uint32_t bbase = sbase + (p == 1 ? OFF_BL : OFF_BH) + b_lane_off;
        #pragma unroll
        for (int kc = 0; kc < 4; kc++) {
            uint32_t a0, a1, a2, a3;
            ldsm_x4(a0, a1, a2, a3, abase + kc * 32);
            #pragma unroll
            for (int np = 0; np < 4; np++) {      // n-tile pairs (2np, 2np+1)
                uint32_t b0, b1, b2, b3;
                ldsm_x4(b0, b1, b2, b3, bbase + np * 16 * ASTRIDE + kc * 32);
                mma16816(acc[2*np][0], acc[2*np][1], acc[2*np][2], acc[2*np][3],
                         a0, a1, a2, a3, b0, b1);
                mma16816(acc[2*np+1][0], acc[2*np+1][1], acc[2*np+1][2], acc[2*np+1][3],
                         a0, a1, a2, a3, b2, b3);
            }
        }
    }

    __syncthreads();   // all warps done reading A/B smem

    // ---- stage D into smem (reuse A region): [128][STAGE_STRIDE] floats ----
    {
        float* stage = (float*)smem;
        const int g = lane >> 2;       // 0..7
        const int t = lane & 3;        // 0..3
        #pragma unroll
        for (int nt = 0; nt < 8; nt++) {
            const int c = nt * 8 + 2 * t;
            float2* p0 = (float2*)&stage[(16 * wid + g) * STAGE_STRIDE + c];
            float2* p1 = (float2*)&stage[(16 * wid + 8 + g) * STAGE_STRIDE + c];
            *p0 = make_float2(acc[nt][0], acc[nt][1]);
            *p1 = make_float2(acc[nt][2], acc[nt][3]);
        }
    }
    __syncthreads();

    // ---- scatter: 2 threads per row, 8 x red.v4 each (32 floats) ----
    {
        const float* stage = (const float*)smem;
        const int row  = tid >> 1;
        const int half = tid & 1;
        if (row < mrem) {
            const int orow = __ldg(&omap[(size_t)k * M_PAIRS + m0 + row]);
            float* dst = out + (size_t)orow * C_OUT + half * 32;
            const float* src = stage + row * STAGE_STRIDE + half * 32;
            #pragma unroll
            for (int j = 0; j < 8; j++) {
                float4 v = *(const float4*)(src + j * 4);
                asm volatile("red.global.add.v4.f32 [%0], {%1, %2, %3, %4};"
                             :: "l"(dst + j * 4), "f"(v.x), "f"(v.y), "f"(v.z), "f"(v.w)
                             : "memory");
            }
        }
    }
}

// ---------------------------------------------------------------------------
// Launch
// ---------------------------------------------------------------------------
extern "C" void kernel_launch(void* const* d_in, const int* in_sizes, int n_in,
                              void* d_out, int out_size) {
    const float* in_feats = (const float*)d_in[0];
    const float* kernel   = (const float*)d_in[1];
    const float* bias     = (const float*)d_in[2];
    const int*   imap     = (const int*)d_in[3];
    const int*   omap     = (const int*)d_in[4];
    float* out = (float*)d_out;
    (void)in_sizes; (void)n_in; (void)out_size;

    cudaFuncSetAttribute(conv_mma_kernel, cudaFuncAttributeMaxDynamicSharedMemorySize,
                         SMEM_BYTES);

    split_feats_kernel<<<4096, 256>>>(in_feats, N_IN * C_IN / 4);
    split_weights_kernel<<<(K_VOL * C_IN * C_OUT + 255) / 256, 256>>>(kernel);
    init_bias_kernel<<<2048, 256>>>(out, bias, N_OUT * C_OUT / 4);

    conv_mma_kernel<<<K_VOL * TILES_PER_K, 256, SMEM_BYTES>>>(imap, omap, out);
}

// round 4
// speedup vs baseline: 3.3631x; 2.0720x over previous
#include <cuda_runtime.h>
#include <cuda_bf16.h>
#include <cstdint>

// ---------------------------------------------------------------------------
// Problem constants
// ---------------------------------------------------------------------------
#define K_VOL    27
#define M_PAIRS  100000
#define C_IN     64
#define C_OUT    64
#define N_IN     200000
#define N_OUT    200000

#define TILE_M   128
#define TILES_PER_K ((M_PAIRS + TILE_M - 1) / TILE_M)   // 782

// bf16 hi/lo scratch (device globals: allocation-free scratch)
__device__ __nv_bfloat16 g_A_hi[(size_t)N_IN * C_IN];
__device__ __nv_bfloat16 g_A_lo[(size_t)N_IN * C_IN];
__device__ __nv_bfloat16 g_B_hi[K_VOL * C_IN * C_OUT];  // transposed: [k][co][ci]
__device__ __nv_bfloat16 g_B_lo[K_VOL * C_IN * C_OUT];

// ---------------------------------------------------------------------------
// smem layout (bytes). Row stride padded 128B -> 144B for conflict-free LDSM.
// ---------------------------------------------------------------------------
#define ASTRIDE   144
#define OFF_AH    0
#define OFF_AL    18432
#define OFF_BH    36864
#define OFF_BL    46080
#define SMEM_BYTES 55296
#define STAGE_STRIDE 72   // floats (stage reuses the A region: 128*72*4 = 36864 B)

__device__ __forceinline__ uint32_t smem_u32(const void* p) {
    uint32_t a;
    asm("{ .reg .u64 t; cvta.to.shared.u64 t, %1; cvt.u32.u64 %0, t; }" : "=r"(a) : "l"(p));
    return a;
}

__device__ __forceinline__ void ldsm_x4(uint32_t& r0, uint32_t& r1, uint32_t& r2, uint32_t& r3,
                                        uint32_t addr) {
    asm volatile("ldmatrix.sync.aligned.m8n8.x4.shared.b16 {%0,%1,%2,%3}, [%4];"
                 : "=r"(r0), "=r"(r1), "=r"(r2), "=r"(r3) : "r"(addr));
}

__device__ __forceinline__ void mma16816(float* c,
                                         uint32_t a0, uint32_t a1, uint32_t a2, uint32_t a3,
                                         uint32_t b0, uint32_t b1) {
    asm volatile(
        "mma.sync.aligned.m16n8k16.row.col.f32.bf16.bf16.f32 "
        "{%0,%1,%2,%3}, {%4,%5,%6,%7}, {%8,%9}, {%0,%1,%2,%3};"
        : "+f"(c[0]), "+f"(c[1]), "+f"(c[2]), "+f"(c[3])
        : "r"(a0), "r"(a1), "r"(a2), "r"(a3), "r"(b0), "r"(b1));
}

// ---------------------------------------------------------------------------
// Kernel A: split fp32 features into bf16 hi + lo
// ---------------------------------------------------------------------------
__global__ void split_feats_kernel(const float* __restrict__ in, int total4) {
    int idx = blockIdx.x * blockDim.x + threadIdx.x;
    int stride = gridDim.x * blockDim.x;
    const float4* in4 = (const float4*)in;
    __nv_bfloat162* hi2 = (__nv_bfloat162*)g_A_hi;
    __nv_bfloat162* lo2 = (__nv_bfloat162*)g_A_lo;
    for (int i = idx; i < total4; i += stride) {
        float4 v = in4[i];
        __nv_bfloat16 h0 = __float2bfloat16_rn(v.x);
        __nv_bfloat16 h1 = __float2bfloat16_rn(v.y);
        __nv_bfloat16 h2 = __float2bfloat16_rn(v.z);
        __nv_bfloat16 h3 = __float2bfloat16_rn(v.w);
        __nv_bfloat16 l0 = __float2bfloat16_rn(v.x - __bfloat162float(h0));
        __nv_bfloat16 l1 = __float2bfloat16_rn(v.y - __bfloat162float(h1));
        __nv_bfloat16 l2 = __float2bfloat16_rn(v.z - __bfloat162float(h2));
        __nv_bfloat16 l3 = __float2bfloat16_rn(v.w - __bfloat162float(h3));
        hi2[i * 2 + 0] = __halves2bfloat162(h0, h1);
        hi2[i * 2 + 1] = __halves2bfloat162(h2, h3);
        lo2[i * 2 + 0] = __halves2bfloat162(l0, l1);
        lo2[i * 2 + 1] = __halves2bfloat162(l2, l3);
    }
}

// ---------------------------------------------------------------------------
// Kernel B: split + transpose weights: g_B[k][co][ci] = split(W[k][ci][co])
// ---------------------------------------------------------------------------
__global__ void split_weights_kernel(const float* __restrict__ W) {
    int idx = blockIdx.x * blockDim.x + threadIdx.x;
    if (idx >= K_VOL * C_IN * C_OUT) return;
    int k  = idx / (C_IN * C_OUT);
    int r  = idx % (C_IN * C_OUT);
    int ci = r / C_OUT;
    int co = r % C_OUT;
    float x = W[idx];
    __nv_bfloat16 h = __float2bfloat16_rn(x);
    __nv_bfloat16 l = __float2bfloat16_rn(x - __bfloat162float(h));
    int didx = k * (C_IN * C_OUT) + co * C_IN + ci;
    g_B_hi[didx] = h;
    g_B_lo[didx] = l;
}

// ---------------------------------------------------------------------------
// Kernel C: out[row][c] = bias[c]
// ---------------------------------------------------------------------------
__global__ void init_bias_kernel(float* __restrict__ out, const float* __restrict__ bias,
                                 int total4) {
    const float4* b4 = (const float4*)bias;
    int idx = blockIdx.x * blockDim.x + threadIdx.x;
    int stride = gridDim.x * blockDim.x;
    for (int i = idx; i < total4; i += stride)
        ((float4*)out)[i] = b4[i & 15];
}

// ---------------------------------------------------------------------------
// Kernel D: per (k, m-tile): coalesced gather -> HMMA bf16-split -> coalesced
// red.v4 scatter.  256 threads (8 warps). Warp w computes rows 16w..16w+15.
// ---------------------------------------------------------------------------
__global__ __launch_bounds__(256, 3)
void conv_mma_kernel(const int* __restrict__ imap, const int* __restrict__ omap,
                     float* __restrict__ out) {
    extern __shared__ char smem[];
    const uint32_t sbase = smem_u32(smem);

    const int tid  = threadIdx.x;
    const int wid  = tid >> 5;
    const int lane = tid & 31;

    const int b    = blockIdx.x;
    const int k    = b / TILES_PER_K;
    const int tile = b % TILES_PER_K;
    const int m0   = tile * TILE_M;
    const int mrem = min(TILE_M, M_PAIRS - m0);

    const int* imap_k = imap + (size_t)k * M_PAIRS + m0;
    const int* omap_k = omap + (size_t)k * M_PAIRS + m0;

    // ---- load B tiles: 1024 uint4 tasks (chunk fastest -> coalesced) ----
    #pragma unroll
    for (int p = 0; p < 4; p++) {
        const int task  = p * 256 + tid;
        const int chunk = task & 7;
        const int row   = (task >> 3) & 63;
        const bool lo   = task >= 512;
        const uint4* src = (const uint4*)((lo ? g_B_lo : g_B_hi) + (size_t)k * 4096 + row * 64);
        *(uint4*)(smem + (lo ? OFF_BL : OFF_BH) + row * ASTRIDE + chunk * 16) = src[chunk];
    }

    // ---- gather A rows: 2048 uint4 tasks, 8 lanes per row (coalesced) ----
    #pragma unroll
    for (int p = 0; p < 8; p++) {
        const int task  = p * 256 + tid;
        const int chunk = task & 7;
        const int row   = (task >> 3) & 127;
        const bool lo   = task >= 1024;
        uint4 v = make_uint4(0, 0, 0, 0);
        if (row < mrem) {
            const int grow = __ldg(&imap_k[row]);
            v = ((const uint4*)((lo ? g_A_lo : g_A_hi) + (size_t)grow * C_IN))[chunk];
        }
        *(uint4*)(smem + (lo ? OFF_AL : OFF_AH) + row * ASTRIDE + chunk * 16) = v;
    }
    __syncthreads();

    // ---- per-lane ldmatrix address offsets ----
    const int a_row  = (lane & 7) + ((lane >> 3) & 1) * 8;
    const int a_koff = (lane >> 4) * 8;
    const uint32_t a_lane_off = (uint32_t)((16 * wid + a_row) * ASTRIDE + a_koff * 2);
    const int b_row  = (lane & 7) + ((lane >> 4) ? 8 : 0);
    const int b_koff = ((lane >> 3) & 1) * 8;
    const uint32_t b_lane_off = (uint32_t)(b_row * ASTRIDE + b_koff * 2);

    // ---- accumulators: 8 n-tiles x 4 regs ----
    float acc[8][4];
    #pragma unroll
    for (int nt = 0; nt < 8; nt++)
        #pragma unroll
        for (int j = 0; j < 4; j++)
            acc[nt][j] = 0.f;

    // ---- fused 3-product loop: per kc load Ah,Al once; per np load Bh,Bl ----
    #pragma unroll
    for (int kc = 0; kc < 4; kc++) {
        uint32_t ah0, ah1, ah2, ah3, al0, al1, al2, al3;
        ldsm_x4(ah0, ah1, ah2, ah3, sbase + OFF_AH + a_lane_off + kc * 32);
        ldsm_x4(al0, al1, al2, al3, sbase + OFF_AL + a_lane_off + kc * 32);
        #pragma unroll
        for (int np = 0; np < 4; np++) {
            const uint32_t boff = b_lane_off + np * 16 * ASTRIDE + kc * 32;
            uint32_t b0, b1, b2, b3;
            ldsm_x4(b0, b1, b2, b3, sbase + OFF_BH + boff);
            mma16816(acc[2*np],     ah0, ah1, ah2, ah3, b0, b1);
            mma16816(acc[2*np + 1], ah0, ah1, ah2, ah3, b2, b3);
            mma16816(acc[2*np],     al0, al1, al2, al3, b0, b1);
            mma16816(acc[2*np + 1], al0, al1, al2, al3, b2, b3);
            ldsm_x4(b0, b1, b2, b3, sbase + OFF_BL + boff);
            mma16816(acc[2*np],     ah0, ah1, ah2, ah3, b0, b1);
            mma16816(acc[2*np + 1], ah0, ah1, ah2, ah3, b2, b3);
        }
    }

    __syncthreads();   // all warps done reading A/B smem

    // ---- stage D into smem (reuse A region): [128][STAGE_STRIDE] floats ----
    {
        float* stage = (float*)smem;
        const int g = lane >> 2;       // 0..7
        const int t = lane & 3;        // 0..3
        #pragma unroll
        for (int nt = 0; nt < 8; nt++) {
            const int c = nt * 8 + 2 * t;
            *(float2*)&stage[(16 * wid + g) * STAGE_STRIDE + c]     = make_float2(acc[nt][0], acc[nt][1]);
            *(float2*)&stage[(16 * wid + 8 + g) * STAGE_STRIDE + c] = make_float2(acc[nt][2], acc[nt][3]);
        }
    }
    __syncthreads();

    // ---- scatter: 2048 red.v4 tasks, 16 lanes per row (coalesced) ----
    {
        const float* stage = (const float*)smem;
        #pragma unroll
        for (int p = 0; p < 8; p++) {
            const int task  = p * 256 + tid;
            const int chunk = task & 15;
            const int row   = task >> 4;
            if (row < mrem) {
                const int orow = __ldg(&omap_k[row]);
                float4 v = *(const float4*)(stage + row * STAGE_STRIDE + chunk * 4);
                asm volatile("red.global.add.v4.f32 [%0], {%1, %2, %3, %4};"
                             :: "l"(out + (size_t)orow * C_OUT + chunk * 4),
                                "f"(v.x), "f"(v.y), "f"(v.z), "f"(v.w)
                             : "memory");
            }
        }
    }
}

// ---------------------------------------------------------------------------
// Launch
// ---------------------------------------------------------------------------
extern "C" void kernel_launch(void* const* d_in, const int* in_sizes, int n_in,
                              void* d_out, int out_size) {
    const float* in_feats = (const float*)d_in[0];
    const float* kernel   = (const float*)d_in[1];
    const float* bias     = (const float*)d_in[2];
    const int*   imap     = (const int*)d_in[3];
    const int*   omap     = (const int*)d_in[4];
    float* out = (float*)d_out;
    (void)in_sizes; (void)n_in; (void)out_size;

    cudaFuncSetAttribute(conv_mma_kernel, cudaFuncAttributeMaxDynamicSharedMemorySize,
                         SMEM_BYTES);

    split_feats_kernel<<<4096, 256>>>(in_feats, N_IN * C_IN / 4);
    split_weights_kernel<<<(K_VOL * C_IN * C_OUT + 255) / 256, 256>>>(kernel);
    init_bias_kernel<<<2048, 256>>>(out, bias, N_OUT * C_OUT / 4);

    conv_mma_kernel<<<K_VOL * TILES_PER_K, 256, SMEM_BYTES>>>(imap, omap, out);
}

// round 5
// speedup vs baseline: 4.2442x; 1.2620x over previous
#include <cuda_runtime.h>
#include <cuda_bf16.h>
#include <cstdint>

// ---------------------------------------------------------------------------
// Problem constants
// ---------------------------------------------------------------------------
#define K_VOL    27
#define M_PAIRS  100000
#define C_IN     64
#define C_OUT    64
#define N_IN     200000
#define N_OUT    200000

#define TILE_M   128
#define TILES_PER_K ((M_PAIRS + TILE_M - 1) / TILE_M)   // 782
#define TOTAL_TILES (K_VOL * TILES_PER_K)               // 21114
#define GRID_P   296                                     // 2 blocks/SM * 148
#define BASE_T   (TOTAL_TILES / GRID_P)                  // 71
#define EXTRA_T  (TOTAL_TILES - GRID_P * BASE_T)         // 98

// bf16 hi/lo scratch (device globals: allocation-free scratch)
__device__ __nv_bfloat16 g_A_hi[(size_t)N_IN * C_IN];
__device__ __nv_bfloat16 g_A_lo[(size_t)N_IN * C_IN];
__device__ __nv_bfloat16 g_B_hi[K_VOL * C_IN * C_OUT];  // transposed: [k][co][ci]
__device__ __nv_bfloat16 g_B_lo[K_VOL * C_IN * C_OUT];

// ---------------------------------------------------------------------------
// smem layout (bytes). 144B row stride for conflict-free LDSM.
//   buf0 : A hi[128*144] + A lo[128*144] = 36864      [0      .. 36864)
//   buf1 : same                                        [36864  .. 73728)
//   Bl   : 64*144 = 9216                               [73728  .. 82944)
//   Bht  : 64*144 = 9216 (transient, k-change only)    [82944  .. 92160)
//   stage reuses current buf: 128 rows * 72 floats
// ---------------------------------------------------------------------------
#define ASTRIDE   144
#define BUF_SZ    36864
#define OFF_LO    18432
#define OFF_BL2   73728
#define OFF_BHT   82944
#define SMEM_BYTES 92160
#define STAGE_STRIDE 72   // floats

__device__ __forceinline__ uint32_t smem_u32(const void* p) {
    uint32_t a;
    asm("{ .reg .u64 t; cvta.to.shared.u64 t, %1; cvt.u32.u64 %0, t; }" : "=r"(a) : "l"(p));
    return a;
}

__device__ __forceinline__ void ldsm_x4(uint32_t& r0, uint32_t& r1, uint32_t& r2, uint32_t& r3,
                                        uint32_t addr) {
    asm volatile("ldmatrix.sync.aligned.m8n8.x4.shared.b16 {%0,%1,%2,%3}, [%4];"
                 : "=r"(r0), "=r"(r1), "=r"(r2), "=r"(r3) : "r"(addr));
}

__device__ __forceinline__ void mma16816(float* c,
                                         uint32_t a0, uint32_t a1, uint32_t a2, uint32_t a3,
                                         uint32_t b0, uint32_t b1) {
    asm volatile(
        "mma.sync.aligned.m16n8k16.row.col.f32.bf16.bf16.f32 "
        "{%0,%1,%2,%3}, {%4,%5,%6,%7}, {%8,%9}, {%0,%1,%2,%3};"
        : "+f"(c[0]), "+f"(c[1]), "+f"(c[2]), "+f"(c[3])
        : "r"(a0), "r"(a1), "r"(a2), "r"(a3), "r"(b0), "r"(b1));
}

__device__ __forceinline__ void cp_async16(uint32_t dst, const void* src, uint32_t sz) {
    asm volatile("cp.async.cg.shared.global [%0], [%1], 16, %2;"
                 :: "r"(dst), "l"(src), "r"(sz) : "memory");
}

// ---------------------------------------------------------------------------
// Kernel A: split fp32 features into bf16 hi + lo
// ---------------------------------------------------------------------------
__global__ void split_feats_kernel(const float* __restrict__ in, int total4) {
    int idx = blockIdx.x * blockDim.x + threadIdx.x;
    int stride = gridDim.x * blockDim.x;
    const float4* in4 = (const float4*)in;
    __nv_bfloat162* hi2 = (__nv_bfloat162*)g_A_hi;
    __nv_bfloat162* lo2 = (__nv_bfloat162*)g_A_lo;
    for (int i = idx; i < total4; i += stride) {
        float4 v = in4[i];
        __nv_bfloat16 h0 = __float2bfloat16_rn(v.x);
        __nv_bfloat16 h1 = __float2bfloat16_rn(v.y);
        __nv_bfloat16 h2 = __float2bfloat16_rn(v.z);
        __nv_bfloat16 h3 = __float2bfloat16_rn(v.w);
        __nv_bfloat16 l0 = __float2bfloat16_rn(v.x - __bfloat162float(h0));
        __nv_bfloat16 l1 = __float2bfloat16_rn(v.y - __bfloat162float(h1));
        __nv_bfloat16 l2 = __float2bfloat16_rn(v.z - __bfloat162float(h2));
        __nv_bfloat16 l3 = __float2bfloat16_rn(v.w - __bfloat162float(h3));
        hi2[i * 2 + 0] = __halves2bfloat162(h0, h1);
        hi2[i * 2 + 1] = __halves2bfloat162(h2, h3);
        lo2[i * 2 + 0] = __halves2bfloat162(l0, l1);
        lo2[i * 2 + 1] = __halves2bfloat162(l2, l3);
    }
}

// ---------------------------------------------------------------------------
// Kernel B: split + transpose weights: g_B[k][co][ci] = split(W[k][ci][co])
// ---------------------------------------------------------------------------
__global__ void split_weights_kernel(const float* __restrict__ W) {
    int idx = blockIdx.x * blockDim.x + threadIdx.x;
    if (idx >= K_VOL * C_IN * C_OUT) return;
    int k  = idx / (C_IN * C_OUT);
    int r  = idx % (C_IN * C_OUT);
    int ci = r / C_OUT;
    int co = r % C_OUT;
    float x = W[idx];
    __nv_bfloat16 h = __float2bfloat16_rn(x);
    __nv_bfloat16 l = __float2bfloat16_rn(x - __bfloat162float(h));
    int didx = k * (C_IN * C_OUT) + co * C_IN + ci;
    g_B_hi[didx] = h;
    g_B_lo[didx] = l;
}

// ---------------------------------------------------------------------------
// Kernel C: out[row][c] = bias[c]
// ---------------------------------------------------------------------------
__global__ void init_bias_kernel(float* __restrict__ out, const float* __restrict__ bias,
                                 int total4) {
    const float4* b4 = (const float4*)bias;
    int idx = blockIdx.x * blockDim.x + threadIdx.x;
    int stride = gridDim.x * blockDim.x;
    for (int i = idx; i < total4; i += stride)
        ((float4*)out)[i] = b4[i & 15];
}

// ---------------------------------------------------------------------------
// nrow preload: imap row indices for the 4 gather rows this thread services
// ---------------------------------------------------------------------------
__device__ __forceinline__ void load_nrow(const int* __restrict__ imap, int t, int tid,
                                          int nrow[4]) {
    const int k    = t / TILES_PER_K;
    const int m0   = (t % TILES_PER_K) * TILE_M;
    const int mrem = min(TILE_M, M_PAIRS - m0);
    const int* imk = imap + (size_t)k * M_PAIRS + m0;
    #pragma unroll
    for (int q = 0; q < 4; q++) {
        const int r = q * 32 + (tid >> 3);
        nrow[q] = (r < mrem) ? __ldg(&imk[r]) : -1;
    }
}

// issue 8 LDGSTS.128 for tile t's A (hi+lo) into buf at bufoff, then commit
__device__ __forceinline__ void prefetch_A(uint32_t sbase, uint32_t bufoff, int t, int tid,
                                           const int nrow[4]) {
    const int m0   = (t % TILES_PER_K) * TILE_M;
    const int mrem = min(TILE_M, M_PAIRS - m0);
    const int chunk = tid & 7;
    #pragma unroll
    for (int p = 0; p < 8; p++) {
        const int q   = p & 3;
        const int row = q * 32 + (tid >> 3);
        const bool lo = p >= 4;
        const int gr  = nrow[q];
        const char* src = (const char*)(lo ? g_A_lo : g_A_hi)
                          + ((size_t)(gr < 0 ? 0 : gr)) * 128 + chunk * 16;
        const uint32_t dst = sbase + bufoff + (lo ? OFF_LO : 0) + row * ASTRIDE + chunk * 16;
        cp_async16(dst, src, (row < mrem) ? 16u : 0u);
    }
    asm volatile("cp.async.commit_group;" ::: "memory");
}

// ---------------------------------------------------------------------------
// Kernel D: persistent gather->MMA->scatter. 256 threads, warp grid 4m x 2n.
// ---------------------------------------------------------------------------
__global__ __launch_bounds__(256, 2)
void conv_persist_kernel(const int* __restrict__ imap, const int* __restrict__ omap,
                         float* __restrict__ out) {
    extern __shared__ char smem[];
    const uint32_t sbase = smem_u32(smem);

    const int tid  = threadIdx.x;
    const int wid  = tid >> 5;
    const int lane = tid & 31;
    const int mi   = wid >> 1;      // 0..3 : rows 32*mi .. +31
    const int ni   = wid & 1;       // 0..1 : cols 32*ni .. +31

    const int b   = blockIdx.x;
    const int nt_ = BASE_T + (b < EXTRA_T);
    const int t0  = b * BASE_T + min(b, EXTRA_T);

    // ldmatrix lane offsets
    const int a_row  = (lane & 7) + ((lane >> 3) & 1) * 8;
    const int a_koff = (lane >> 4) * 8;
    const int b_row  = (lane & 7) + ((lane >> 4) ? 8 : 0);
    const int b_koff = ((lane >> 3) & 1) * 8;

    uint32_t bh[4][2][4];           // weight-hi fragments: [kc][npair][4]
    int kcur = -1;

    // ---- prologue: prefetch tile t0, preload nrow for t0+1 ----
    int nrow[4];
    load_nrow(imap, t0, tid, nrow);
    prefetch_A(sbase, 0, t0, tid, nrow);
    if (nt_ > 1) load_nrow(imap, t0 + 1, tid, nrow);

    for (int i = 0; i < nt_; i++) {
        const int t    = t0 + i;
        const int k    = t / TILES_PER_K;
        const int m0   = (t % TILES_PER_K) * TILE_M;
        const int mrem = min(TILE_M, M_PAIRS - m0);
        const uint32_t bufoff = (uint32_t)(i & 1) * BUF_SZ;

        asm volatile("cp.async.wait_group 0;" ::: "memory");
        __syncthreads();            // A[t] ready; prior Bl/stage reads done

        // ---- k-change: load Bl smem + Bh regs (<= 2x per block) ----
        if (k != kcur) {
            kcur = k;
            const int chunk = tid & 7;
            #pragma unroll
            for (int p = 0; p < 4; p++) {
                const int row = ((p * 256 + tid) >> 3) & 63;
                const bool lo = p >= 2;
                const uint4* src = (const uint4*)((lo ? g_B_lo : g_B_hi)
                                                  + (size_t)k * 4096 + row * 64) + chunk;
                *(uint4*)(smem + (lo ? OFF_BL2 : OFF_BHT) + row * ASTRIDE + chunk * 16) = *src;
            }
            __syncthreads();
            #pragma unroll
            for (int kc = 0; kc < 4; kc++)
                #pragma unroll
                for (int np = 0; np < 2; np++) {
                    const uint32_t addr = sbase + OFF_BHT
                        + (32 * ni + 16 * np + b_row) * ASTRIDE + b_koff * 2 + kc * 32;
                    ldsm_x4(bh[kc][np][0], bh[kc][np][1], bh[kc][np][2], bh[kc][np][3], addr);
                }
        }

        // ---- issue prefetch of next tile; rotate nrow ----
        if (i + 1 < nt_) prefetch_A(sbase, bufoff ^ BUF_SZ, t + 1, tid, nrow);
        if (i + 2 < nt_) load_nrow(imap, t + 2, tid, nrow);

        // ---- preload omap rows for this tile (covered by MMA) ----
        int orow[8];
        {
            const int* omk = omap + (size_t)k * M_PAIRS + m0;
            #pragma unroll
            for (int p = 0; p < 8; p++) {
                const int r = p * 16 + (tid >> 4);
                orow[p] = (r < mrem) ? __ldg(&omk[r]) : -1;
            }
        }

        // ---- MMA: warp m32 x n32, 3-product bf16 split ----
        float acc[2][4][4];
        #pragma unroll
        for (int ms = 0; ms < 2; ms++)
            #pragma unroll
            for (int nt2 = 0; nt2 < 4; nt2++)
                #pragma unroll
                for (int j = 0; j < 4; j++)
                    acc[ms][nt2][j] = 0.f;

        #pragma unroll
        for (int kc = 0; kc < 4; kc++) {
            uint32_t ah[2][4], al[2][4], bl[2][4];
            #pragma unroll
            for (int ms = 0; ms < 2; ms++) {
                const uint32_t abase = sbase + bufoff
                    + (32 * mi + 16 * ms + a_row) * ASTRIDE + a_koff * 2 + kc * 32;
                ldsm_x4(ah[ms][0], ah[ms][1], ah[ms][2], ah[ms][3], abase);
                ldsm_x4(al[ms][0], al[ms][1], al[ms][2], al[ms][3], abase + OFF_LO);
            }
            #pragma unroll
            for (int np = 0; np < 2; np++) {
                const uint32_t baddr = sbase + OFF_BL2
                    + (32 * ni + 16 * np + b_row) * ASTRIDE + b_koff * 2 + kc * 32;
                ldsm_x4(bl[np][0], bl[np][1], bl[np][2], bl[np][3], baddr);
            }
            #pragma unroll
            for (int ms = 0; ms < 2; ms++)
                #pragma unroll
                for (int np = 0; np < 2; np++) {
                    mma16816(acc[ms][2*np],   ah[ms][0], ah[ms][1], ah[ms][2], ah[ms][3],
                             bh[kc][np][0], bh[kc][np][1]);
                    mma16816(acc[ms][2*np+1], ah[ms][0], ah[ms][1], ah[ms][2], ah[ms][3],
                             bh[kc][np][2], bh[kc][np][3]);
                    mma16816(acc[ms][2*np],   al[ms][0], al[ms][1], al[ms][2], al[ms][3],
                             bh[kc][np][0], bh[kc][np][1]);
                    mma16816(acc[ms][2*np+1], al[ms][0], al[ms][1], al[ms][2], al[ms][3],
                             bh[kc][np][2], bh[kc][np][3]);
                    mma16816(acc[ms][2*np],   ah[ms][0], ah[ms][1], ah[ms][2], ah[ms][3],
                             bl[np][0], bl[np][1]);
                    mma16816(acc[ms][2*np+1], ah[ms][0], ah[ms][1], ah[ms][2], ah[ms][3],
                             bl[np][2], bl[np][3]);
                }
        }

        __syncthreads();            // all LDSM of buf done; safe to overwrite as stage

        // ---- stage D into current buf: [128][72] floats ----
        {
            float* stage = (float*)(smem + bufoff);
            const int g  = lane >> 2;
            const int tq = lane & 3;
            #pragma unroll
            for (int ms = 0; ms < 2; ms++)
                #pragma unroll
                for (int nt2 = 0; nt2 < 4; nt2++) {
                    const int r0 = 32 * mi + 16 * ms + g;
                    const int c  = 32 * ni + nt2 * 8 + 2 * tq;
                    *(float2*)&stage[r0 * STAGE_STRIDE + c] =
                        make_float2(acc[ms][nt2][0], acc[ms][nt2][1]);
                    *(float2*)&stage[(r0 + 8) * STAGE_STRIDE + c] =
                        make_float2(acc[ms][nt2][2], acc[ms][nt2][3]);
                }
        }
        __syncthreads();

        // ---- scatter: 16 lanes per row, red.v4 ----
        {
            const float* stage = (const float*)(smem + bufoff);
            const int chunk = tid & 15;
            #pragma unroll
            for (int p = 0; p < 8; p++) {
                const int r = p * 16 + (tid >> 4);
                if (orow[p] >= 0) {
                    float4 v = *(const float4*)(stage + r * STAGE_STRIDE + chunk * 4);
                    asm volatile("red.global.add.v4.f32 [%0], {%1, %2, %3, %4};"
                                 :: "l"(out + (size_t)orow[p] * C_OUT + chunk * 4),
                                    "f"(v.x), "f"(v.y), "f"(v.z), "f"(v.w)
                                 : "memory");
                }
            }
        }
    }
}

// ---------------------------------------------------------------------------
// Launch
// ---------------------------------------------------------------------------
extern "C" void kernel_launch(void* const* d_in, const int* in_sizes, int n_in,
                              void* d_out, int out_size) {
    const float* in_feats = (const float*)d_in[0];
    const float* kernel   = (const float*)d_in[1];
    const float* bias     = (const float*)d_in[2];
    const int*   imap     = (const int*)d_in[3];
    const int*   omap     = (const int*)d_in[4];
    float* out = (float*)d_out;
    (void)in_sizes; (void)n_in; (void)out_size;

    cudaFuncSetAttribute(conv_persist_kernel, cudaFuncAttributeMaxDynamicSharedMemorySize,
                         SMEM_BYTES);

    split_feats_kernel<<<4096, 256>>>(in_feats, N_IN * C_IN / 4);
    split_weights_kernel<<<(K_VOL * C_IN * C_OUT + 255) / 256, 256>>>(kernel);
    init_bias_kernel<<<2048, 256>>>(out, bias, N_OUT * C_OUT / 4);

    conv_persist_kernel<<<GRID_P, 256, SMEM_BYTES>>>(imap, omap, out);
}